// round 4
// baseline (speedup 1.0000x reference)
#include <cuda_runtime.h>

// Problem constants
#define Bsz   2048
#define Hdim  1024
#define Lseq  96
#define Vsz   96

// GEMM tiling
#define BM 128
#define BN 128
#define BK 16

// Scratch (device globals -- sanctioned scratch path, no allocations)
__device__ float g_h0a[(size_t)Bsz * Hdim];
__device__ float g_h0b[(size_t)Bsz * Hdim];
__device__ float g_hs[(size_t)Lseq * Bsz * Hdim];   // h1 history, [t][b][h]

// ---------------------------------------------------------------------------
// Packed fp32x2 helpers (Blackwell FFMA2: 2x fp32 FMA per instruction)
// ---------------------------------------------------------------------------
__device__ __forceinline__ unsigned long long pack2(float lo, float hi) {
    unsigned long long r;
    asm("mov.b64 %0, {%1, %2};" : "=l"(r) : "f"(lo), "f"(hi));
    return r;
}
__device__ __forceinline__ float2 unpack2(unsigned long long v) {
    float2 r;
    asm("mov.b64 {%0, %1}, %2;" : "=f"(r.x), "=f"(r.y) : "l"(v));
    return r;
}
__device__ __forceinline__ void ffma2(unsigned long long& d,
                                      unsigned long long a,
                                      unsigned long long b) {
    asm("fma.rn.f32x2 %0, %1, %2, %0;" : "+l"(d) : "l"(a), "l"(b));
}

// Inner-product over one smem tile: acc[i][jp] accumulates columns (2jp,2jp+1)
__device__ __forceinline__ void compute_tile(unsigned long long acc[8][4],
                                             const float As[BK][BM],
                                             const float Ws[BK][BN],
                                             int tx, int ty) {
#pragma unroll
    for (int k = 0; k < BK; ++k) {
        float a[8];
        *(float4*)&a[0] = *(const float4*)&As[k][ty * 8];
        *(float4*)&a[4] = *(const float4*)&As[k][ty * 8 + 4];
        ulonglong2 b01 = *(const ulonglong2*)&Ws[k][tx * 8];
        ulonglong2 b23 = *(const ulonglong2*)&Ws[k][tx * 8 + 4];
        unsigned long long b2[4] = {b01.x, b01.y, b23.x, b23.y};
#pragma unroll
        for (int i = 0; i < 8; ++i) {
            unsigned long long a2 = pack2(a[i], a[i]);
#pragma unroll
            for (int jp = 0; jp < 4; ++jp) ffma2(acc[i][jp], a2, b2[jp]);
        }
    }
}

// ---------------------------------------------------------------------------
// RNN layer GEMM:  out = tanh( A1@W1^T [+ A2@W2^T] + bias_a + bias_b
//                              [+ x[:,t] * wih] )
// A: [*, Hdim] rows of state, W: [Hdim, Hdim] row-major (out, in).
// ---------------------------------------------------------------------------
__global__ void __launch_bounds__(256, 1)
rnn_layer_kernel(float* __restrict__ out,
                 const float* __restrict__ A1, const float* __restrict__ W1, int kt1,
                 const float* __restrict__ A2, const float* __restrict__ W2, int kt2,
                 const float* __restrict__ bias_a, const float* __restrict__ bias_b,
                 const float* __restrict__ xseq, const float* __restrict__ wih, int t)
{
    __shared__ float As[BK][BM];
    __shared__ float Ws[BK][BN];
    const int tid = threadIdx.x;
    const int tx = tid & 15, ty = tid >> 4;
    const int m0 = blockIdx.x * BM;
    const int n0 = blockIdx.y * BN;
    const int lrow0 = tid >> 2, lrow1 = lrow0 + 64;
    const int lcol  = (tid & 3) << 2;

    unsigned long long acc[8][4];
#pragma unroll
    for (int i = 0; i < 8; ++i)
#pragma unroll
        for (int j = 0; j < 4; ++j) acc[i][j] = 0ull;

    for (int pass = 0; pass < 2; ++pass) {
        const float* A = pass ? A2 : A1;
        const float* W = pass ? W2 : W1;
        const int ktiles = pass ? kt2 : kt1;
        if (ktiles == 0) continue;

        const float* Ar0 = A + (size_t)(m0 + lrow0) * Hdim + lcol;
        const float* Ar1 = A + (size_t)(m0 + lrow1) * Hdim + lcol;
        const float* Wr0 = W + (size_t)(n0 + lrow0) * Hdim + lcol;
        const float* Wr1 = W + (size_t)(n0 + lrow1) * Hdim + lcol;

        float4 a0 = *(const float4*)Ar0;
        float4 a1 = *(const float4*)Ar1;
        float4 w0 = *(const float4*)Wr0;
        float4 w1 = *(const float4*)Wr1;

        for (int kt = 0; kt < ktiles; ++kt) {
            As[lcol+0][lrow0]=a0.x; As[lcol+1][lrow0]=a0.y; As[lcol+2][lrow0]=a0.z; As[lcol+3][lrow0]=a0.w;
            As[lcol+0][lrow1]=a1.x; As[lcol+1][lrow1]=a1.y; As[lcol+2][lrow1]=a1.z; As[lcol+3][lrow1]=a1.w;
            Ws[lcol+0][lrow0]=w0.x; Ws[lcol+1][lrow0]=w0.y; Ws[lcol+2][lrow0]=w0.z; Ws[lcol+3][lrow0]=w0.w;
            Ws[lcol+0][lrow1]=w1.x; Ws[lcol+1][lrow1]=w1.y; Ws[lcol+2][lrow1]=w1.z; Ws[lcol+3][lrow1]=w1.w;
            __syncthreads();
            if (kt + 1 < ktiles) {
                const int off = (kt + 1) * BK;
                a0 = *(const float4*)(Ar0 + off);
                a1 = *(const float4*)(Ar1 + off);
                w0 = *(const float4*)(Wr0 + off);
                w1 = *(const float4*)(Wr1 + off);
            }
            compute_tile(acc, As, Ws, tx, ty);
            __syncthreads();
        }
    }

    // Fused epilogue: rank-1 x*Wih term + biases + tanh
    const int mrow = m0 + ty * 8;
    const int ncol = n0 + tx * 8;
    float bias8[8], wih8[8];
#pragma unroll
    for (int j = 0; j < 8; ++j) {
        bias8[j] = bias_a[ncol + j] + bias_b[ncol + j];
        wih8[j]  = wih ? wih[ncol + j] : 0.0f;
    }
#pragma unroll
    for (int i = 0; i < 8; ++i) {
        const float xv = xseq ? xseq[(size_t)(mrow + i) * Lseq + t] : 0.0f;
        float o[8];
#pragma unroll
        for (int jp = 0; jp < 4; ++jp) {
            float2 f = unpack2(acc[i][jp]);
            o[2*jp] = f.x; o[2*jp+1] = f.y;
        }
#pragma unroll
        for (int j = 0; j < 8; ++j)
            o[j] = tanhf(o[j] + bias8[j] + xv * wih8[j]);
        float4* po = (float4*)(out + (size_t)(mrow + i) * Hdim + ncol);
        po[0] = make_float4(o[0], o[1], o[2], o[3]);
        po[1] = make_float4(o[4], o[5], o[6], o[7]);
    }
}

// ---------------------------------------------------------------------------
// FC GEMM over the full h1 history:  logits[t,b,v] = hs[t,b,:]@fcW[v,:] + fcb[v]
// Writes unadjusted logits directly to d_out in [b, t, v] layout.
// M = Lseq*Bsz rows (m = t*Bsz + b), N = Vsz (96), K = Hdim.
// ---------------------------------------------------------------------------
__global__ void __launch_bounds__(256, 1)
fc_kernel(float* __restrict__ out, const float* __restrict__ A,
          const float* __restrict__ W, const float* __restrict__ bias)
{
    __shared__ float As[BK][BM];
    __shared__ float Ws[BK][BN];
    const int tid = threadIdx.x;
    const int tx = tid & 15, ty = tid >> 4;
    const int m0 = blockIdx.x * BM;
    const int lrow0 = tid >> 2, lrow1 = lrow0 + 64;
    const int lcol  = (tid & 3) << 2;

    unsigned long long acc[8][4];
#pragma unroll
    for (int i = 0; i < 8; ++i)
#pragma unroll
        for (int j = 0; j < 4; ++j) acc[i][j] = 0ull;

    const float* Ar0 = A + (size_t)(m0 + lrow0) * Hdim + lcol;
    const float* Ar1 = A + (size_t)(m0 + lrow1) * Hdim + lcol;
    const float* Wr0 = W + (size_t)lrow0 * Hdim + lcol;            // rows 0..63 always valid
    const bool   w1ok = (lrow1 < Vsz);                             // rows 64..127: guard
    const float* Wr1 = W + (size_t)(w1ok ? lrow1 : 0) * Hdim + lcol;

    const int ktiles = Hdim / BK;
    float4 a0 = *(const float4*)Ar0;
    float4 a1 = *(const float4*)Ar1;
    float4 w0 = *(const float4*)Wr0;
    float4 w1 = w1ok ? *(const float4*)Wr1 : make_float4(0.f,0.f,0.f,0.f);

    for (int kt = 0; kt < ktiles; ++kt) {
        As[lcol+0][lrow0]=a0.x; As[lcol+1][lrow0]=a0.y; As[lcol+2][lrow0]=a0.z; As[lcol+3][lrow0]=a0.w;
        As[lcol+0][lrow1]=a1.x; As[lcol+1][lrow1]=a1.y; As[lcol+2][lrow1]=a1.z; As[lcol+3][lrow1]=a1.w;
        Ws[lcol+0][lrow0]=w0.x; Ws[lcol+1][lrow0]=w0.y; Ws[lcol+2][lrow0]=w0.z; Ws[lcol+3][lrow0]=w0.w;
        Ws[lcol+0][lrow1]=w1.x; Ws[lcol+1][lrow1]=w1.y; Ws[lcol+2][lrow1]=w1.z; Ws[lcol+3][lrow1]=w1.w;
        __syncthreads();
        if (kt + 1 < ktiles) {
            const int off = (kt + 1) * BK;
            a0 = *(const float4*)(Ar0 + off);
            a1 = *(const float4*)(Ar1 + off);
            w0 = *(const float4*)(Wr0 + off);
            w1 = w1ok ? *(const float4*)(Wr1 + off) : make_float4(0.f,0.f,0.f,0.f);
        }
        compute_tile(acc, As, Ws, tx, ty);
        __syncthreads();
    }

    if (tx < Vsz / 8) {                        // tx 0..11 valid (V=96)
        const int ncol = tx * 8;
        float bias8[8];
#pragma unroll
        for (int j = 0; j < 8; ++j) bias8[j] = bias[ncol + j];
#pragma unroll
        for (int i = 0; i < 8; ++i) {
            const int m  = m0 + ty * 8 + i;
            const int tt = m >> 11;            // / Bsz (2048)
            const int b  = m & (Bsz - 1);
            float o[8];
#pragma unroll
            for (int jp = 0; jp < 4; ++jp) {
                float2 f = unpack2(acc[i][jp]);
                o[2*jp] = f.x + bias8[2*jp]; o[2*jp+1] = f.y + bias8[2*jp+1];
            }
            float4* po = (float4*)(out + ((size_t)b * Lseq + tt) * Vsz + ncol);
            po[0] = make_float4(o[0], o[1], o[2], o[3]);
            po[1] = make_float4(o[4], o[5], o[6], o[7]);
        }
    }
}

// ---------------------------------------------------------------------------
// Sequential probability patch: warp per batch element, in-place on d_out.
// Matches jnp.argmax first-index tie-break. Carry = argmax of ADJUSTED row.
// ---------------------------------------------------------------------------
__global__ void adjust_kernel(float* __restrict__ out)
{
    const int gw   = (blockIdx.x * blockDim.x + threadIdx.x) >> 5;
    const int lane = threadIdx.x & 31;
    if (gw >= Bsz) return;
    const size_t base = (size_t)gw * Lseq * Vsz;

    int prev_arg = 0;
    for (int t = 0; t < Lseq; ++t) {
        const size_t r = base + (size_t)t * Vsz;
        float v0 = out[r + lane];
        float v1 = out[r + lane + 32];
        float v2 = out[r + lane + 64];

        float mv = v0; int mi = lane;
        if (v1 > mv) { mv = v1; mi = lane + 32; }
        if (v2 > mv) { mv = v2; mi = lane + 64; }
#pragma unroll
        for (int off = 16; off > 0; off >>= 1) {
            float ov = __shfl_xor_sync(0xffffffffu, mv, off);
            int   oi = __shfl_xor_sync(0xffffffffu, mi, off);
            if (ov > mv || (ov == mv && oi < mi)) { mv = ov; mi = oi; }
        }
        const int cur_arg = mi;   // argmax of UNADJUSTED row

        if (t == 0) { prev_arg = cur_arg; continue; }

        bool modified = false;    // warp-uniform
        if (prev_arg == 0 /*Q*/ && cur_arg != 1 /*U*/) {
            if (lane == 1) { v0 += 0.5f; out[r + 1] = v0; }
            modified = true;
        }
        if (t == Lseq - 1 && cur_arg == 0 /*Q*/) {
            if (lane == 0) { v0 -= 0.5f; out[r + 0] = v0; }
            modified = true;
        }
        if (modified) {           // recompute argmax of adjusted row for carry
            mv = v0; mi = lane;
            if (v1 > mv) { mv = v1; mi = lane + 32; }
            if (v2 > mv) { mv = v2; mi = lane + 64; }
#pragma unroll
            for (int off = 16; off > 0; off >>= 1) {
                float ov = __shfl_xor_sync(0xffffffffu, mv, off);
                int   oi = __shfl_xor_sync(0xffffffffu, mi, off);
                if (ov > mv || (ov == mv && oi < mi)) { mv = ov; mi = oi; }
            }
        }
        prev_arg = mi;
    }
}

// hidden = stack([h0_final, h1_final])
__global__ void hidden_copy(float* __restrict__ out,
                            const float* __restrict__ h0,
                            const float* __restrict__ h1)
{
    const size_t i = (size_t)blockIdx.x * blockDim.x + threadIdx.x;
    if (i < (size_t)Bsz * Hdim) {
        out[i] = h0[i];
        out[(size_t)Bsz * Hdim + i] = h1[i];
    }
}

// ---------------------------------------------------------------------------
extern "C" void kernel_launch(void* const* d_in, const int* in_sizes, int n_in,
                              void* d_out, int out_size)
{
    (void)in_sizes; (void)n_in; (void)out_size;
    const float* x    = (const float*)d_in[0];
    const float* w0ih = (const float*)d_in[1];
    const float* w0hh = (const float*)d_in[2];
    const float* b0ih = (const float*)d_in[3];
    const float* b0hh = (const float*)d_in[4];
    const float* w1ih = (const float*)d_in[5];
    const float* w1hh = (const float*)d_in[6];
    const float* b1ih = (const float*)d_in[7];
    const float* b1hh = (const float*)d_in[8];
    const float* fcW  = (const float*)d_in[9];
    const float* fcb  = (const float*)d_in[10];
    float* out = (float*)d_out;

    float *h0a, *h0b, *hs;
    cudaGetSymbolAddress((void**)&h0a, g_h0a);
    cudaGetSymbolAddress((void**)&h0b, g_h0b);
    cudaGetSymbolAddress((void**)&hs,  g_hs);

    const dim3 grid(Bsz / BM, Hdim / BN);   // 16 x 8 = 128 blocks
    const int  KT = Hdim / BK;              // 64 k-tiles

    for (int t = 0; t < Lseq; ++t) {
        const float* h0_prev = (t & 1) ? h0b : h0a;
        float*       h0_cur  = (t & 1) ? h0a : h0b;

        // layer0: h0 = tanh(h0_prev@W0hh^T + x_t*W0ih + b0ih + b0hh)
        rnn_layer_kernel<<<grid, 256>>>(h0_cur,
                                        h0_prev, w0hh, (t == 0) ? 0 : KT,
                                        nullptr, nullptr, 0,
                                        b0ih, b0hh, x, w0ih, t);

        // layer1: h1 = tanh(h0_cur@W1ih^T + h1_prev@W1hh^T + b1ih + b1hh)
        float*       h1_cur  = hs + (size_t)t * Bsz * Hdim;
        const float* h1_prev = (t == 0) ? nullptr
                                        : hs + (size_t)(t - 1) * Bsz * Hdim;
        rnn_layer_kernel<<<grid, 256>>>(h1_cur,
                                        h0_cur, w1ih, KT,
                                        h1_prev, w1hh, (t == 0) ? 0 : KT,
                                        b1ih, b1hh, nullptr, nullptr, 0);
    }

    // One big FC over the whole h1 history -> unadjusted logits in d_out
    fc_kernel<<<(Lseq * Bsz) / BM, 256>>>(out, hs, fcW, fcb);

    // Sequential in-place probability patch
    adjust_kernel<<<Bsz / 8, 256>>>(out);

    // hidden tail: h0 final lives in h0a (t=95 is odd), h1 final = hs[95]
    hidden_copy<<<(Bsz * Hdim + 255) / 256, 256>>>(
        out + (size_t)Bsz * Lseq * Vsz, h0a,
        hs + (size_t)(Lseq - 1) * Bsz * Hdim);
}

// round 10
// speedup vs baseline: 2.1413x; 2.1413x over previous
#include <cuda_runtime.h>
#include <cuda_bf16.h>
#include <cstdint>

#define Bsz   2048
#define Hdim  1024
#define Lseq  96
#define Vsz   96

#define TM 128
#define TN 128
#define KC 32                 // bf16 K elements per chunk
#define STRIDE_B 80           // padded smem row: 32 bf16 (64B) + 16B pad
#define TILE_SMB (128 * STRIDE_B)          // 10240 B per operand tile
#define STAGE_SMB (4 * TILE_SMB)           // Ahi, Alo, Whi, Wlo
#define SMEM_TOTAL (2 * STAGE_SMB)         // 81920 B, double-buffered

// ---------------------------------------------------------------------------
// Device-global scratch (sanctioned scratch path; no allocations)
// ---------------------------------------------------------------------------
__device__ __nv_bfloat16 g_h0hi[2 * Bsz * Hdim];
__device__ __nv_bfloat16 g_h0lo[2 * Bsz * Hdim];
__device__ __nv_bfloat16 g_hshi[(size_t)Lseq * Bsz * Hdim];
__device__ __nv_bfloat16 g_hslo[(size_t)Lseq * Bsz * Hdim];
__device__ float g_h0f[Bsz * Hdim];
__device__ float g_h1f[Bsz * Hdim];
__device__ __nv_bfloat16 g_w0hh_hi[Hdim * Hdim], g_w0hh_lo[Hdim * Hdim];
__device__ __nv_bfloat16 g_w1ih_hi[Hdim * Hdim], g_w1ih_lo[Hdim * Hdim];
__device__ __nv_bfloat16 g_w1hh_hi[Hdim * Hdim], g_w1hh_lo[Hdim * Hdim];
__device__ __nv_bfloat16 g_fcw_hi[128 * Hdim], g_fcw_lo[128 * Hdim]; // padded to 128 rows
__device__ float g_bias0[Hdim], g_bias1[Hdim];

// ---------------------------------------------------------------------------
// PTX helpers: baseline sm_80+ instructions only (no arch-suffix features)
// ---------------------------------------------------------------------------
__device__ __forceinline__ uint32_t smem_to_u32(const void* p) {
    uint32_t a;
    asm("{ .reg .u64 t; cvta.to.shared.u64 t, %1; cvt.u32.u64 %0, t; }"
        : "=r"(a) : "l"(p));
    return a;
}
__device__ __forceinline__ void cp_async16(uint32_t dst, const void* src) {
    asm volatile("cp.async.cg.shared.global [%0], [%1], 16;"
                 :: "r"(dst), "l"(src));
}
__device__ __forceinline__ void cp_commit() {
    asm volatile("cp.async.commit_group;");
}
template <int N>
__device__ __forceinline__ void cp_wait() {
    asm volatile("cp.async.wait_group %0;" :: "n"(N));
}
__device__ __forceinline__ void ldsm_x4(uint32_t* r, uint32_t addr) {
    asm volatile("ldmatrix.sync.aligned.m8n8.x4.shared.b16 {%0,%1,%2,%3}, [%4];"
                 : "=r"(r[0]), "=r"(r[1]), "=r"(r[2]), "=r"(r[3]) : "r"(addr));
}
__device__ __forceinline__ void mma_bf16(float* d, const uint32_t* a,
                                         uint32_t b0, uint32_t b1) {
    asm volatile(
        "mma.sync.aligned.m16n8k16.row.col.f32.bf16.bf16.f32 "
        "{%0,%1,%2,%3}, {%4,%5,%6,%7}, {%8,%9}, {%0,%1,%2,%3};"
        : "+f"(d[0]), "+f"(d[1]), "+f"(d[2]), "+f"(d[3])
        : "r"(a[0]), "r"(a[1]), "r"(a[2]), "r"(a[3]), "r"(b0), "r"(b1));
}
__device__ __forceinline__ float tanh_fast(float v) {
    float e = __expf(2.0f * v);
    return 1.0f - __fdividef(2.0f, e + 1.0f);
}

// ---------------------------------------------------------------------------
// Main GEMM kernel (HMMA, bf16x3 split emulation of fp32).
//   D[m,n] = sum over 1-2 passes of  A[m,:] . W[n,:]
//   RNN epilogue: tanh(D + bias + x_t*wih) -> bf16 hi/lo (+ optional fp32)
//   FC  epilogue: D + fcb -> d_out[(b*L + t)*V + v]
// ---------------------------------------------------------------------------
template <bool IS_FC>
__global__ void __launch_bounds__(256, 1)
gemm_k(__nv_bfloat16* __restrict__ out_hi, __nv_bfloat16* __restrict__ out_lo,
       float* __restrict__ out_f,
       const __nv_bfloat16* __restrict__ A1h, const __nv_bfloat16* __restrict__ A1l,
       const __nv_bfloat16* __restrict__ W1h, const __nv_bfloat16* __restrict__ W1l, int kc1,
       const __nv_bfloat16* __restrict__ A2h, const __nv_bfloat16* __restrict__ A2l,
       const __nv_bfloat16* __restrict__ W2h, const __nv_bfloat16* __restrict__ W2l, int kc2,
       const float* __restrict__ bias, const float* __restrict__ xseq,
       const float* __restrict__ wih, int t)
{
    extern __shared__ char smem[];
    const uint32_t sb = smem_to_u32(smem);
    const int tid  = threadIdx.x;
    const int wid  = tid >> 5;
    const int lane = tid & 31;
    const int m0 = blockIdx.x * TM;
    const int n0 = IS_FC ? 0 : (blockIdx.y * TN);
    const int wm = (wid & 1) * 64;        // warp M offset within tile
    const int wn = (wid >> 1) * 32;       // warp N offset within tile

    float acc[4][4][4];
#pragma unroll
    for (int i = 0; i < 4; ++i)
#pragma unroll
        for (int j = 0; j < 4; ++j)
#pragma unroll
            for (int q = 0; q < 4; ++q) acc[i][j][q] = 0.0f;

    const int rounds = kc1 + kc2;

    // ---- async loader for round r into stage (r&1) ----
    auto load_round = [&](int r) {
        const bool p2 = (r >= kc1);
        const __nv_bfloat16* Ah = p2 ? A2h : A1h;
        const __nv_bfloat16* Al = p2 ? A2l : A1l;
        const __nv_bfloat16* Wh = p2 ? W2h : W1h;
        const __nv_bfloat16* Wl = p2 ? W2l : W1l;
        const int k0 = (p2 ? r - kc1 : r) * KC;
        const uint32_t sbase = sb + (r & 1) * STAGE_SMB;
#pragma unroll
        for (int i = 0; i < 2; ++i) {
            const int c   = tid + (i << 8);      // 0..511
            const int row = c >> 2;              // 128 rows, 4 x 16B chunks each
            const int c16 = c & 3;
            const size_t gA = (size_t)(m0 + row) * Hdim + k0 + c16 * 8;
            const size_t gW = (size_t)(n0 + row) * Hdim + k0 + c16 * 8;
            const uint32_t so = sbase + row * STRIDE_B + c16 * 16;
            cp_async16(so,                Ah + gA);
            cp_async16(so + TILE_SMB,     Al + gA);
            cp_async16(so + 2 * TILE_SMB, Wh + gW);
            cp_async16(so + 3 * TILE_SMB, Wl + gW);
        }
        cp_commit();
    };

    load_round(0);
    for (int r = 0; r < rounds; ++r) {
        if (r + 1 < rounds) { load_round(r + 1); cp_wait<1>(); }
        else                { cp_wait<0>(); }
        __syncthreads();

        const uint32_t sbase = sb + (r & 1) * STAGE_SMB;
        // ldmatrix lane addressing: rows = lane%16, 16B col block = lane/16
        const uint32_t aA = sbase + (wm + (lane & 15)) * STRIDE_B + ((lane >> 4) << 4);
        const uint32_t aB = sbase + 2 * TILE_SMB +
                            (wn + (lane & 15)) * STRIDE_B + ((lane >> 4) << 4);
#pragma unroll
        for (int ks = 0; ks < 2; ++ks) {        // two k16 steps per 32-chunk
            uint32_t ah[4][4], al[4][4];
#pragma unroll
            for (int im = 0; im < 4; ++im) {
                ldsm_x4(ah[im], aA + im * 16 * STRIDE_B + ks * 32);
                ldsm_x4(al[im], aA + TILE_SMB + im * 16 * STRIDE_B + ks * 32);
            }
            uint32_t bh[2][4], bl[2][4];
#pragma unroll
            for (int j2 = 0; j2 < 2; ++j2) {
                ldsm_x4(bh[j2], aB + j2 * 16 * STRIDE_B + ks * 32);
                ldsm_x4(bl[j2], aB + TILE_SMB + j2 * 16 * STRIDE_B + ks * 32);
            }
#pragma unroll
            for (int im = 0; im < 4; ++im)
#pragma unroll
                for (int jn = 0; jn < 4; ++jn) {
                    const int j2 = jn >> 1, js = jn & 1;
                    // hi*hi + hi*lo + lo*hi  (bf16x3 fp32 emulation)
                    mma_bf16(acc[im][jn], ah[im], bh[j2][js], bh[j2][js + 2]);
                    mma_bf16(acc[im][jn], ah[im], bl[j2][js], bl[j2][js + 2]);
                    mma_bf16(acc[im][jn], al[im], bh[j2][js], bh[j2][js + 2]);
                }
        }
        __syncthreads();   // stage reuse fence (next-next load overwrites it)
    }

    // ---- Epilogue ----
    const int lm  = lane >> 2;          // fragment row 0..7
    const int lc2 = (lane & 3) << 1;    // fragment col pair

    if (!IS_FC) {
#pragma unroll
        for (int im = 0; im < 4; ++im) {
            const int r0 = m0 + wm + im * 16 + lm;
            const int r1 = r0 + 8;
            float xv0 = 0.0f, xv1 = 0.0f;
            if (wih) {
                xv0 = __ldg(xseq + (size_t)r0 * Lseq + t);
                xv1 = __ldg(xseq + (size_t)r1 * Lseq + t);
            }
#pragma unroll
            for (int jn = 0; jn < 4; ++jn) {
                const int c = n0 + wn + jn * 8 + lc2;
                const float bb0 = __ldg(bias + c), bb1 = __ldg(bias + c + 1);
                float wi0 = 0.0f, wi1 = 0.0f;
                if (wih) { wi0 = __ldg(wih + c); wi1 = __ldg(wih + c + 1); }
                const float o00 = tanh_fast(acc[im][jn][0] + bb0 + xv0 * wi0);
                const float o01 = tanh_fast(acc[im][jn][1] + bb1 + xv0 * wi1);
                const float o10 = tanh_fast(acc[im][jn][2] + bb0 + xv1 * wi0);
                const float o11 = tanh_fast(acc[im][jn][3] + bb1 + xv1 * wi1);

                __nv_bfloat162 h0p, h1p, l0p, l1p;
                h0p.x = __float2bfloat16(o00);
                h0p.y = __float2bfloat16(o01);
                h1p.x = __float2bfloat16(o10);
                h1p.y = __float2bfloat16(o11);
                l0p.x = __float2bfloat16(o00 - __bfloat162float(h0p.x));
                l0p.y = __float2bfloat16(o01 - __bfloat162float(h0p.y));
                l1p.x = __float2bfloat16(o10 - __bfloat162float(h1p.x));
                l1p.y = __float2bfloat16(o11 - __bfloat162float(h1p.y));

                const size_t o0 = (size_t)r0 * Hdim + c;
                const size_t o1 = (size_t)r1 * Hdim + c;
                *(__nv_bfloat162*)(out_hi + o0) = h0p;
                *(__nv_bfloat162*)(out_hi + o1) = h1p;
                *(__nv_bfloat162*)(out_lo + o0) = l0p;
                *(__nv_bfloat162*)(out_lo + o1) = l1p;
                if (out_f) {
                    *(float2*)(out_f + o0) = make_float2(o00, o01);
                    *(float2*)(out_f + o1) = make_float2(o10, o11);
                }
            }
        }
    } else {
#pragma unroll
        for (int im = 0; im < 4; ++im) {
            const int r0 = m0 + wm + im * 16 + lm;
            const int r1 = r0 + 8;
            const int tt0 = r0 >> 11, b0i = r0 & (Bsz - 1);
            const int tt1 = r1 >> 11, b1i = r1 & (Bsz - 1);
#pragma unroll
            for (int jn = 0; jn < 4; ++jn) {
                const int c = wn + jn * 8 + lc2;
                if (c >= Vsz) continue;   // padded W cols 96..127: computed zeros
                const float bb0 = __ldg(bias + c), bb1 = __ldg(bias + c + 1);
                *(float2*)(out_f + ((size_t)b0i * Lseq + tt0) * Vsz + c) =
                    make_float2(acc[im][jn][0] + bb0, acc[im][jn][1] + bb1);
                *(float2*)(out_f + ((size_t)b1i * Lseq + tt1) * Vsz + c) =
                    make_float2(acc[im][jn][2] + bb0, acc[im][jn][3] + bb1);
            }
        }
    }
}

// ---------------------------------------------------------------------------
// Prep kernels
// ---------------------------------------------------------------------------
__global__ void split_k(__nv_bfloat16* __restrict__ hi, __nv_bfloat16* __restrict__ lo,
                        const float* __restrict__ src, int n)
{
    const int i = blockIdx.x * blockDim.x + threadIdx.x;
    if (i < n) {
        const float x = src[i];
        const __nv_bfloat16 h = __float2bfloat16(x);
        hi[i] = h;
        lo[i] = __float2bfloat16(x - __bfloat162float(h));
    }
}

// FC weight split, padded to 128 rows (rows 96..127 = 0)
__global__ void split_fc(__nv_bfloat16* __restrict__ hi, __nv_bfloat16* __restrict__ lo,
                         const float* __restrict__ src)
{
    const int i = blockIdx.x * blockDim.x + threadIdx.x;
    if (i < 128 * Hdim) {
        const int row = i >> 10;
        const float x = (row < Vsz) ? src[i] : 0.0f;
        const __nv_bfloat16 h = __float2bfloat16(x);
        hi[i] = h;
        lo[i] = __float2bfloat16(x - __bfloat162float(h));
    }
}

__global__ void bias_prep(float* __restrict__ b0, float* __restrict__ b1,
                          const float* a0, const float* c0,
                          const float* a1, const float* c1)
{
    const int i = threadIdx.x + blockIdx.x * blockDim.x;
    if (i < Hdim) { b0[i] = a0[i] + c0[i]; b1[i] = a1[i] + c1[i]; }
}

// t=0 layer0: h0 = tanh(x_0 * wih + bias0)   (h_prev = 0, no GEMM)
__global__ void l0_init(__nv_bfloat16* __restrict__ hhi, __nv_bfloat16* __restrict__ hlo,
                        const float* __restrict__ x, const float* __restrict__ wih,
                        const float* __restrict__ bias)
{
    const int i = blockIdx.x * blockDim.x + threadIdx.x;
    if (i < Bsz * Hdim) {
        const int b = i >> 10, n = i & (Hdim - 1);
        const float o = tanh_fast(x[b * Lseq + 0] * wih[n] + bias[n]);
        const __nv_bfloat16 h = __float2bfloat16(o);
        hhi[i] = h;
        hlo[i] = __float2bfloat16(o - __bfloat162float(h));
    }
}

// ---------------------------------------------------------------------------
// Sequential probability patch (unchanged from passing R4 kernel)
// ---------------------------------------------------------------------------
__global__ void adjust_kernel(float* __restrict__ out)
{
    const int gw   = (blockIdx.x * blockDim.x + threadIdx.x) >> 5;
    const int lane = threadIdx.x & 31;
    if (gw >= Bsz) return;
    const size_t base = (size_t)gw * Lseq * Vsz;

    int prev_arg = 0;
    for (int t = 0; t < Lseq; ++t) {
        const size_t r = base + (size_t)t * Vsz;
        float v0 = out[r + lane];
        float v1 = out[r + lane + 32];
        float v2 = out[r + lane + 64];

        float mv = v0; int mi = lane;
        if (v1 > mv) { mv = v1; mi = lane + 32; }
        if (v2 > mv) { mv = v2; mi = lane + 64; }
#pragma unroll
        for (int off = 16; off > 0; off >>= 1) {
            float ov = __shfl_xor_sync(0xffffffffu, mv, off);
            int   oi = __shfl_xor_sync(0xffffffffu, mi, off);
            if (ov > mv || (ov == mv && oi < mi)) { mv = ov; mi = oi; }
        }
        const int cur_arg = mi;

        if (t == 0) { prev_arg = cur_arg; continue; }

        bool modified = false;
        if (prev_arg == 0 && cur_arg != 1) {
            if (lane == 1) { v0 += 0.5f; out[r + 1] = v0; }
            modified = true;
        }
        if (t == Lseq - 1 && cur_arg == 0) {
            if (lane == 0) { v0 -= 0.5f; out[r + 0] = v0; }
            modified = true;
        }
        if (modified) {
            mv = v0; mi = lane;
            if (v1 > mv) { mv = v1; mi = lane + 32; }
            if (v2 > mv) { mv = v2; mi = lane + 64; }
#pragma unroll
            for (int off = 16; off > 0; off >>= 1) {
                float ov = __shfl_xor_sync(0xffffffffu, mv, off);
                int   oi = __shfl_xor_sync(0xffffffffu, mi, off);
                if (ov > mv || (ov == mv && oi < mi)) { mv = ov; mi = oi; }
            }
        }
        prev_arg = mi;
    }
}

__global__ void hidden_copy(float* __restrict__ out,
                            const float* __restrict__ h0,
                            const float* __restrict__ h1)
{
    const size_t i = (size_t)blockIdx.x * blockDim.x + threadIdx.x;
    if (i < (size_t)Bsz * Hdim) {
        out[i] = h0[i];
        out[(size_t)Bsz * Hdim + i] = h1[i];
    }
}

// ---------------------------------------------------------------------------
extern "C" void kernel_launch(void* const* d_in, const int* in_sizes, int n_in,
                              void* d_out, int out_size)
{
    (void)in_sizes; (void)n_in; (void)out_size;
    const float* x    = (const float*)d_in[0];
    const float* w0ih = (const float*)d_in[1];
    const float* w0hh = (const float*)d_in[2];
    const float* b0ih = (const float*)d_in[3];
    const float* b0hh = (const float*)d_in[4];
    const float* w1ih = (const float*)d_in[5];
    const float* w1hh = (const float*)d_in[6];
    const float* b1ih = (const float*)d_in[7];
    const float* b1hh = (const float*)d_in[8];
    const float* fcW  = (const float*)d_in[9];
    const float* fcb  = (const float*)d_in[10];
    float* out = (float*)d_out;

    __nv_bfloat16 *h0hi, *h0lo, *hshi, *hslo;
    __nv_bfloat16 *w0hhH, *w0hhL, *w1ihH, *w1ihL, *w1hhH, *w1hhL, *fcwH, *fcwL;
    float *h0f, *h1f, *bias0, *bias1;
    cudaGetSymbolAddress((void**)&h0hi, g_h0hi);
    cudaGetSymbolAddress((void**)&h0lo, g_h0lo);
    cudaGetSymbolAddress((void**)&hshi, g_hshi);
    cudaGetSymbolAddress((void**)&hslo, g_hslo);
    cudaGetSymbolAddress((void**)&h0f,  g_h0f);
    cudaGetSymbolAddress((void**)&h1f,  g_h1f);
    cudaGetSymbolAddress((void**)&w0hhH, g_w0hh_hi);
    cudaGetSymbolAddress((void**)&w0hhL, g_w0hh_lo);
    cudaGetSymbolAddress((void**)&w1ihH, g_w1ih_hi);
    cudaGetSymbolAddress((void**)&w1ihL, g_w1ih_lo);
    cudaGetSymbolAddress((void**)&w1hhH, g_w1hh_hi);
    cudaGetSymbolAddress((void**)&w1hhL, g_w1hh_lo);
    cudaGetSymbolAddress((void**)&fcwH, g_fcw_hi);
    cudaGetSymbolAddress((void**)&fcwL, g_fcw_lo);
    cudaGetSymbolAddress((void**)&bias0, g_bias0);
    cudaGetSymbolAddress((void**)&bias1, g_bias1);

    cudaFuncSetAttribute(gemm_k<false>, cudaFuncAttributeMaxDynamicSharedMemorySize, SMEM_TOTAL);
    cudaFuncSetAttribute(gemm_k<true>,  cudaFuncAttributeMaxDynamicSharedMemorySize, SMEM_TOTAL);

    // ---- Prep: split weights into bf16 hi/lo; combine biases ----
    const int nW = Hdim * Hdim;
    split_k<<<(nW + 255) / 256, 256>>>(w0hhH, w0hhL, w0hh, nW);
    split_k<<<(nW + 255) / 256, 256>>>(w1ihH, w1ihL, w1ih, nW);
    split_k<<<(nW + 255) / 256, 256>>>(w1hhH, w1hhL, w1hh, nW);
    split_fc<<<(128 * Hdim + 255) / 256, 256>>>(fcwH, fcwL, fcW);
    bias_prep<<<4, 256>>>(bias0, bias1, b0ih, b0hh, b1ih, b1hh);

    const dim3 grid_rnn(Bsz / TM, Hdim / TN);   // 16 x 8 = 128 CTAs
    const int  KCHUNKS = Hdim / KC;             // 32

    // ---- t=0 ----
    l0_init<<<(Bsz * Hdim + 255) / 256, 256>>>(h0hi, h0lo, x, w0ih, bias0);
    gemm_k<false><<<grid_rnn, 256, SMEM_TOTAL>>>(
        hshi, hslo, nullptr,
        h0hi, h0lo, w1ihH, w1ihL, KCHUNKS,
        nullptr, nullptr, nullptr, nullptr, 0,
        bias1, nullptr, nullptr, 0);

    // ---- t = 1..95 ----
    for (int t = 1; t < Lseq; ++t) {
        const int cur = t & 1, prv = cur ^ 1;
        __nv_bfloat16* h0hc = h0hi + (size_t)cur * Bsz * Hdim;
        __nv_bfloat16* h0lc = h0lo + (size_t)cur * Bsz * Hdim;
        const __nv_bfloat16* h0hp = h0hi + (size_t)prv * Bsz * Hdim;
        const __nv_bfloat16* h0lp = h0lo + (size_t)prv * Bsz * Hdim;
        const bool last = (t == Lseq - 1);

        // layer0: h0 = tanh(h0_prev@W0hh^T + x_t*w0ih + bias0)
        gemm_k<false><<<grid_rnn, 256, SMEM_TOTAL>>>(
            h0hc, h0lc, last ? h0f : nullptr,
            h0hp, h0lp, w0hhH, w0hhL, KCHUNKS,
            nullptr, nullptr, nullptr, nullptr, 0,
            bias0, x, w0ih, t);

        // layer1: h1 = tanh(h0@W1ih^T + h1_prev@W1hh^T + bias1)
        __nv_bfloat16* hsh = hshi + (size_t)t * Bsz * Hdim;
        __nv_bfloat16* hsl = hslo + (size_t)t * Bsz * Hdim;
        gemm_k<false><<<grid_rnn, 256, SMEM_TOTAL>>>(
            hsh, hsl, last ? h1f : nullptr,
            h0hc, h0lc, w1ihH, w1ihL, KCHUNKS,
            hshi + (size_t)(t - 1) * Bsz * Hdim,
            hslo + (size_t)(t - 1) * Bsz * Hdim, w1hhH, w1hhL, KCHUNKS,
            bias1, nullptr, nullptr, t);
    }

    // ---- FC over full h1 history -> logits (permuted to [b, t, v]) ----
    gemm_k<true><<<dim3(Lseq * Bsz / TM, 1), 256, SMEM_TOTAL>>>(
        nullptr, nullptr, out,
        hshi, hslo, fcwH, fcwL, KCHUNKS,
        nullptr, nullptr, nullptr, nullptr, 0,
        fcb, nullptr, nullptr, 0);

    // ---- sequential probability patch + hidden tail ----
    adjust_kernel<<<Bsz / 8, 256>>>(out);
    hidden_copy<<<(Bsz * Hdim + 255) / 256, 256>>>(
        out + (size_t)Bsz * Lseq * Vsz, h0f, h1f);
}